// round 6
// baseline (speedup 1.0000x reference)
#include <cuda_runtime.h>
#include <cuda_bf16.h>
#include <math_constants.h>

// Problem constants
#define NQ   65536          // 16*4096 query vectors
#define DIM  64
#define NK   8192           // codebook size
#define TQ   64             // queries per block (argmin kernel)
#define TK   128            // codes per k-tile

// Output layout (flattened fp32, reference return order)
#define ZQ_OFF   0
#define LOSS_OFF 4194304
#define ENC_OFF  4194305
#define CS_OFF   4259841
#define EA_OFF   4268033
#define W_OFF    4792321

typedef unsigned long long ull;

// ------------------------- scratch (device globals; no allocs) ------------
__device__ float  g_zn[(size_t)NQ * DIM];     // normalized z (16 MB)
__device__ float  g_w2[NK];                   // per-code squared norm
__device__ int    g_enc[NQ];                  // argmin indices
__device__ float  g_bins[NK];                 // histogram
__device__ float  g_es[(size_t)NK * DIM];     // embed_sum (2 MB)
__device__ double g_loss;                     // loss accumulator

// ------------------------- f32x2 helpers ----------------------------------
__device__ __forceinline__ void fma2(ull& d, ull a, ull b) {
    asm("fma.rn.f32x2 %0, %1, %2, %0;" : "+l"(d) : "l"(a), "l"(b));
}
__device__ __forceinline__ void unpack2(ull v, float& lo, float& hi) {
    asm("mov.b64 {%0, %1}, %2;" : "=f"(lo), "=f"(hi) : "l"(v));
}
// swap halves of an f32x2 register pair (ALU-pipe PRMT copies)
__device__ __forceinline__ ull swap2(ull a) {
    unsigned lo, hi, slo, shi;
    asm("mov.b64 {%0, %1}, %2;" : "=r"(lo), "=r"(hi) : "l"(a));
    asm("prmt.b32 %0, %1, %1, 0x3210;" : "=r"(slo) : "r"(hi));
    asm("prmt.b32 %0, %1, %1, 0x3210;" : "=r"(shi) : "r"(lo));
    ull r;
    asm("mov.b64 %0, {%1, %2};" : "=l"(r) : "r"(slo), "r"(shi));
    return r;
}

// ------------------------- kernel 0: zero scratch --------------------------
__global__ void k_zero() {
    int idx = blockIdx.x * blockDim.x + threadIdx.x;
    if (idx < NK * DIM) g_es[idx] = 0.0f;
    int j = idx - NK * DIM;
    if (j >= 0 && j < NK) g_bins[j] = 0.0f;
    if (idx == 0) g_loss = 0.0;
}

// ------------------------- kernel 1: normalize z ---------------------------
__global__ void k_normz(const float* __restrict__ Z) {
    int warp = (blockIdx.x * blockDim.x + threadIdx.x) >> 5;
    int lane = threadIdx.x & 31;
    if (warp >= NQ) return;
    float2 v = reinterpret_cast<const float2*>(Z)[(size_t)warp * 32 + lane];
    float ss = v.x * v.x + v.y * v.y;
    #pragma unroll
    for (int off = 16; off > 0; off >>= 1)
        ss += __shfl_xor_sync(0xffffffffu, ss, off);
    float inv = 1.0f / fmaxf(sqrtf(ss), 1e-12f);
    reinterpret_cast<float2*>(g_zn)[(size_t)warp * 32 + lane] =
        make_float2(v.x * inv, v.y * inv);
}

// ------------------------- kernel 2: w2 ------------------------------------
__global__ void k_w2(const float* __restrict__ W) {
    int warp = (blockIdx.x * blockDim.x + threadIdx.x) >> 5;
    int lane = threadIdx.x & 31;
    if (warp >= NK) return;
    float2 v = reinterpret_cast<const float2*>(W)[(size_t)warp * 32 + lane];
    float ss = v.x * v.x + v.y * v.y;
    #pragma unroll
    for (int off = 16; off > 0; off >>= 1)
        ss += __shfl_xor_sync(0xffffffffu, ss, off);
    if (lane == 0) g_w2[warp] = ss;
}

// ------------------------- kernel 3: argmin (f32x2 SGEMM-argmin) -----------
// Block: 256 threads = 16(tx over k) x 16(ty over q). Micro-tile 4q x 8k
// (16 ull accs = 32 regs) -> low reg pressure -> 3 blocks/SM + prefetch slack.
// Z natural packed q-pairs, W natural packed k-pairs. Each 2q x 2k tile:
//   accD += a       * b   -> (qe*ke, qo*ko)
//   accA += swap(a) * b   -> (qo*ke, qe*ko)
__global__ __launch_bounds__(256, 3)
void k_argmin(const float* __restrict__ W) {
    extern __shared__ float sm[];
    float* sZ  = sm;                      // 64 * 64 floats  (d-major, q rows)
    float* sW  = sm + 64 * 64;            // 64 * 128 floats (d-major, k rows)
    float* sw2 = sW + 64 * 128;           // 128 floats

    const int tid = threadIdx.x;
    const int tx = tid & 15;
    const int ty = tid >> 4;
    const int q0 = blockIdx.x * TQ;

    // Load Z tile transposed: sZ[d][q] = zn[q0+q][d], q in [0,64)
    {
        const float4* Z4 = reinterpret_cast<const float4*>(g_zn) + (size_t)q0 * 16;
        #pragma unroll
        for (int rep = 0; rep < 4; ++rep) {
            int idx = rep * 256 + tid;          // 1024 float4 total
            int c4 = idx >> 6, q = idx & 63;
            float4 v = Z4[(size_t)q * 16 + c4];
            sZ[(c4 * 4 + 0) * 64 + q] = v.x;
            sZ[(c4 * 4 + 1) * 64 + q] = v.y;
            sZ[(c4 * 4 + 2) * 64 + q] = v.z;
            sZ[(c4 * 4 + 3) * 64 + q] = v.w;
        }
    }

    // local q slot r in [0,4) -> global q = q0 + ty*4 + r
    float minv[4];
    int   mini[4];
    #pragma unroll
    for (int i = 0; i < 4; ++i) { minv[i] = CUDART_INF_F; mini[i] = 0; }

    for (int kt = 0; kt < NK / TK; ++kt) {
        __syncthreads();  // previous tile compute done (and sZ visible on kt==0)
        // Load W tile transposed: sW[d][k] = W[kt*128+k][d]
        {
            const float4* W4 = reinterpret_cast<const float4*>(W) + (size_t)kt * TK * 16;
            #pragma unroll
            for (int rep = 0; rep < 8; ++rep) {
                int idx = rep * 256 + tid;
                int c4 = idx >> 7, k = idx & 127;
                float4 v = W4[(size_t)k * 16 + c4];
                sW[(c4 * 4 + 0) * 128 + k] = v.x;
                sW[(c4 * 4 + 1) * 128 + k] = v.y;
                sW[(c4 * 4 + 2) * 128 + k] = v.z;
                sW[(c4 * 4 + 3) * 128 + k] = v.w;
            }
            if (tid < 128) sw2[tid] = g_w2[kt * 128 + tid];
        }
        __syncthreads();

        ull accD[8], accA[8];   // [qp*4 + kp], qp in 0..1, kp in 0..3
        #pragma unroll
        for (int i = 0; i < 8; ++i) { accD[i] = 0ull; accA[i] = 0ull; }

        #pragma unroll 8
        for (int d = 0; d < 64; ++d) {
            // B: codes tx*8 + {0..7} as 4 natural pairs -> 2 x LDS.128
            const ull* bp = reinterpret_cast<const ull*>(&sW[d * 128]) + tx * 4;
            ull b0 = bp[0], b1 = bp[1], b2 = bp[2], b3 = bp[3];
            // A: queries ty*4 + {0..3} as 2 natural pairs -> 1 x LDS.128
            const ull* ap = reinterpret_cast<const ull*>(&sZ[d * 64]) + ty * 2;
            ull a0 = ap[0], a1 = ap[1];
            ull s0 = swap2(a0), s1 = swap2(a1);

            fma2(accD[0], a0, b0);  fma2(accA[0], s0, b0);
            fma2(accD[1], a0, b1);  fma2(accA[1], s0, b1);
            fma2(accD[2], a0, b2);  fma2(accA[2], s0, b2);
            fma2(accD[3], a0, b3);  fma2(accA[3], s0, b3);
            fma2(accD[4], a1, b0);  fma2(accA[4], s1, b0);
            fma2(accD[5], a1, b1);  fma2(accA[5], s1, b1);
            fma2(accD[6], a1, b2);  fma2(accA[6], s1, b2);
            fma2(accD[7], a1, b3);  fma2(accA[7], s1, b3);
        }

        // epilogue. accD=(qe*ke,qo*ko), accA=(qo*ke,qe*ko).
        // kj ascending, ke before ko, strict < : lowest index wins ties.
        int kbase = kt * 128 + tx * 8;
        #pragma unroll
        for (int qp = 0; qp < 2; ++qp) {
            #pragma unroll
            for (int kj = 0; kj < 4; ++kj) {
                float de, dh, ae, ah;
                unpack2(accD[qp * 4 + kj], de, dh);
                unpack2(accA[qp * 4 + kj], ae, ah);
                float w2e = sw2[tx * 8 + kj * 2];
                float w2o = sw2[tx * 8 + kj * 2 + 1];
                int ke = kbase + kj * 2;
                // q_even (slot 2qp):  (ke: de) (ko: ah)
                float se0 = fmaf(-2.0f, de, w2e);
                float se1 = fmaf(-2.0f, ah, w2o);
                if (se0 < minv[qp * 2]) { minv[qp * 2] = se0; mini[qp * 2] = ke; }
                if (se1 < minv[qp * 2]) { minv[qp * 2] = se1; mini[qp * 2] = ke + 1; }
                // q_odd (slot 2qp+1): (ke: ae) (ko: dh)
                float so0 = fmaf(-2.0f, ae, w2e);
                float so1 = fmaf(-2.0f, dh, w2o);
                if (so0 < minv[qp * 2 + 1]) { minv[qp * 2 + 1] = so0; mini[qp * 2 + 1] = ke; }
                if (so1 < minv[qp * 2 + 1]) { minv[qp * 2 + 1] = so1; mini[qp * 2 + 1] = ke + 1; }
            }
        }
    }

    // reduce across the 16 tx-threads (same half-warp, width 16)
    #pragma unroll
    for (int off = 8; off > 0; off >>= 1) {
        #pragma unroll
        for (int r = 0; r < 4; ++r) {
            float ov = __shfl_down_sync(0xffffffffu, minv[r], off, 16);
            int   oi = __shfl_down_sync(0xffffffffu, mini[r], off, 16);
            if (ov < minv[r] || (ov == minv[r] && oi < mini[r])) {
                minv[r] = ov; mini[r] = oi;
            }
        }
    }
    if (tx == 0) {
        #pragma unroll
        for (int r = 0; r < 4; ++r)
            g_enc[q0 + ty * 4 + r] = mini[r];
    }
}

// ------------------------- kernel 4: scatter / z_q / loss ------------------
__global__ void k_scatter(const float* __restrict__ W, float* __restrict__ out) {
    int warp = (blockIdx.x * blockDim.x + threadIdx.x) >> 5;
    int lane = threadIdx.x & 31;
    if (warp >= NQ) return;
    int e = g_enc[warp];

    float2 wv = reinterpret_cast<const float2*>(W)[(size_t)e * 32 + lane];
    float2 zv = reinterpret_cast<const float2*>(g_zn)[(size_t)warp * 32 + lane];
    float d0 = wv.x - zv.x, d1 = wv.y - zv.y;
    reinterpret_cast<float2*>(out + ZQ_OFF)[(size_t)warp * 32 + lane] =
        make_float2(zv.x + d0, zv.y + d1);

    atomicAdd(&g_es[(size_t)e * 64 + 2 * lane],     zv.x);
    atomicAdd(&g_es[(size_t)e * 64 + 2 * lane + 1], zv.y);

    float part = d0 * d0 + d1 * d1;
    #pragma unroll
    for (int off = 16; off > 0; off >>= 1)
        part += __shfl_xor_sync(0xffffffffu, part, off);
    if (lane == 0) {
        atomicAdd(&g_bins[e], 1.0f);
        atomicAdd(&g_loss, (double)part);
        out[ENC_OFF + warp] = (float)e;
    }
}

// ------------------------- kernel 5: per-code EMA updates ------------------
__global__ void k_update(const float* __restrict__ W,
                         const float* __restrict__ CS,
                         const float* __restrict__ EA,
                         float* __restrict__ out) {
    int warp = (blockIdx.x * blockDim.x + threadIdx.x) >> 5;
    int lane = threadIdx.x & 31;
    if (blockIdx.x == 0 && threadIdx.x == 0) {
        out[LOSS_OFF] = (float)(0.25 * (g_loss / (double)((size_t)NQ * DIM)));
    }
    if (warp >= NK) return;
    int k = warp;

    float b = g_bins[k];
    float2 es = reinterpret_cast<const float2*>(g_es)[(size_t)k * 32 + lane];
    float2 ea = reinterpret_cast<const float2*>(EA)[(size_t)k * 32 + lane];

    out[EA_OFF + (size_t)k * 64 + 2 * lane]     = ea.x * 0.99f + 0.01f * es.x;
    out[EA_OFF + (size_t)k * 64 + 2 * lane + 1] = ea.y * 0.99f + 0.01f * es.y;

    float bc = (b == 0.0f) ? 1.0f : b;
    float vx = es.x / bc, vy = es.y / bc;
    float ss = vx * vx + vy * vy;
    #pragma unroll
    for (int off = 16; off > 0; off >>= 1)
        ss += __shfl_xor_sync(0xffffffffu, ss, off);
    float inv = 1.0f / fmaxf(sqrtf(ss), 1e-12f);

    float2 wv = reinterpret_cast<const float2*>(W)[(size_t)k * 32 + lane];
    float enx = (b == 0.0f) ? wv.x : vx * inv;
    float eny = (b == 0.0f) ? wv.y : vy * inv;

    float nwx = wv.x * 0.99f + 0.01f * enx;
    float nwy = wv.y * 0.99f + 0.01f * eny;
    float ss2 = nwx * nwx + nwy * nwy;
    #pragma unroll
    for (int off = 16; off > 0; off >>= 1)
        ss2 += __shfl_xor_sync(0xffffffffu, ss2, off);
    float inv2 = 1.0f / fmaxf(sqrtf(ss2), 1e-12f);

    out[W_OFF + (size_t)k * 64 + 2 * lane]     = nwx * inv2;
    out[W_OFF + (size_t)k * 64 + 2 * lane + 1] = nwy * inv2;

    if (lane == 0) out[CS_OFF + k] = CS[k] * 0.99f + 0.01f * b;
}

// ------------------------- launch -------------------------------------------
extern "C" void kernel_launch(void* const* d_in, const int* in_sizes, int n_in,
                              void* d_out, int out_size) {
    const float* z  = (const float*)d_in[0];
    const float* w  = (const float*)d_in[1];
    const float* cs = (const float*)d_in[2];
    const float* ea = (const float*)d_in[3];
    float* out = (float*)d_out;

    const int smem_bytes = (64 * 64 + 64 * 128 + 128) * sizeof(float);  // 49664
    cudaFuncSetAttribute(k_argmin, cudaFuncAttributeMaxDynamicSharedMemorySize,
                         smem_bytes);

    k_zero<<<(NK * DIM + NK + 255) / 256, 256>>>();
    k_normz<<<NQ / 8, 256>>>(z);
    k_w2<<<NK / 8, 256>>>(w);
    k_argmin<<<NQ / TQ, 256, smem_bytes>>>(w);
    k_scatter<<<NQ / 8, 256>>>(w, out);
    k_update<<<NK / 8, 256>>>(w, cs, ea, out);
}

// round 7
// speedup vs baseline: 1.0002x; 1.0002x over previous
#include <cuda_runtime.h>
#include <cuda_bf16.h>
#include <math_constants.h>

// Problem constants
#define NQ   65536          // 16*4096 query vectors
#define DIM  64
#define NK   8192           // codebook size
#define TQ   64             // queries per block (argmin kernel)
#define TK   128            // codes per k-tile

// Output layout (flattened fp32, reference return order)
#define ZQ_OFF   0
#define LOSS_OFF 4194304
#define ENC_OFF  4194305
#define CS_OFF   4259841
#define EA_OFF   4268033
#define W_OFF    4792321

typedef unsigned long long ull;

// ------------------------- scratch (device globals; no allocs) ------------
__device__ float  g_zn[(size_t)NQ * DIM];     // normalized z (16 MB)
__device__ float  g_w2[NK];                   // per-code squared norm
__device__ int    g_enc[NQ];                  // argmin indices
__device__ float  g_bins[NK];                 // histogram
__device__ float  g_es[(size_t)NK * DIM];     // embed_sum (2 MB)
__device__ double g_loss;                     // loss accumulator

// ------------------------- f32x2 helpers ----------------------------------
__device__ __forceinline__ void fma2(ull& d, ull a, ull b) {
    asm("fma.rn.f32x2 %0, %1, %2, %0;" : "+l"(d) : "l"(a), "l"(b));
}
__device__ __forceinline__ void unpack2(ull v, float& lo, float& hi) {
    asm("mov.b64 {%0, %1}, %2;" : "=f"(lo), "=f"(hi) : "l"(v));
}
// swap halves of an f32x2 register pair (ALU-pipe PRMT copies)
__device__ __forceinline__ ull swap2(ull a) {
    unsigned lo, hi, slo, shi;
    asm("mov.b64 {%0, %1}, %2;" : "=r"(lo), "=r"(hi) : "l"(a));
    asm("prmt.b32 %0, %1, %1, 0x3210;" : "=r"(slo) : "r"(hi));
    asm("prmt.b32 %0, %1, %1, 0x3210;" : "=r"(shi) : "r"(lo));
    ull r;
    asm("mov.b64 %0, {%1, %2};" : "=l"(r) : "r"(slo), "r"(shi));
    return r;
}

// ------------------------- kernel 0: zero scratch --------------------------
__global__ void k_zero() {
    int idx = blockIdx.x * blockDim.x + threadIdx.x;
    if (idx < NK * DIM) g_es[idx] = 0.0f;
    int j = idx - NK * DIM;
    if (j >= 0 && j < NK) g_bins[j] = 0.0f;
    if (idx == 0) g_loss = 0.0;
}

// ------------------------- kernel 1: normalize z ---------------------------
__global__ void k_normz(const float* __restrict__ Z) {
    int warp = (blockIdx.x * blockDim.x + threadIdx.x) >> 5;
    int lane = threadIdx.x & 31;
    if (warp >= NQ) return;
    float2 v = reinterpret_cast<const float2*>(Z)[(size_t)warp * 32 + lane];
    float ss = v.x * v.x + v.y * v.y;
    #pragma unroll
    for (int off = 16; off > 0; off >>= 1)
        ss += __shfl_xor_sync(0xffffffffu, ss, off);
    float inv = 1.0f / fmaxf(sqrtf(ss), 1e-12f);
    reinterpret_cast<float2*>(g_zn)[(size_t)warp * 32 + lane] =
        make_float2(v.x * inv, v.y * inv);
}

// ------------------------- kernel 2: w2 ------------------------------------
__global__ void k_w2(const float* __restrict__ W) {
    int warp = (blockIdx.x * blockDim.x + threadIdx.x) >> 5;
    int lane = threadIdx.x & 31;
    if (warp >= NK) return;
    float2 v = reinterpret_cast<const float2*>(W)[(size_t)warp * 32 + lane];
    float ss = v.x * v.x + v.y * v.y;
    #pragma unroll
    for (int off = 16; off > 0; off >>= 1)
        ss += __shfl_xor_sync(0xffffffffu, ss, off);
    if (lane == 0) g_w2[warp] = ss;
}

// ------------------------- kernel 3: argmin (f32x2 SGEMM-argmin) -----------
// Block: 256 threads = 16(tx over k) x 16(ty over q). Micro-tile 4q x 8k
// (16 ull accs = 32 regs) -> low reg pressure -> 3 blocks/SM + prefetch slack.
// Z natural packed q-pairs, W natural packed k-pairs. Each 2q x 2k tile:
//   accD += a       * b   -> (qe*ke, qo*ko)
//   accA += swap(a) * b   -> (qo*ke, qe*ko)
__global__ __launch_bounds__(256, 3)
void k_argmin(const float* __restrict__ W) {
    extern __shared__ float sm[];
    float* sZ  = sm;                      // 64 * 64 floats  (d-major, q rows)
    float* sW  = sm + 64 * 64;            // 64 * 128 floats (d-major, k rows)
    float* sw2 = sW + 64 * 128;           // 128 floats

    const int tid = threadIdx.x;
    const int tx = tid & 15;
    const int ty = tid >> 4;
    const int q0 = blockIdx.x * TQ;

    // Load Z tile transposed: sZ[d][q] = zn[q0+q][d], q in [0,64)
    {
        const float4* Z4 = reinterpret_cast<const float4*>(g_zn) + (size_t)q0 * 16;
        #pragma unroll
        for (int rep = 0; rep < 4; ++rep) {
            int idx = rep * 256 + tid;          // 1024 float4 total
            int c4 = idx >> 6, q = idx & 63;
            float4 v = Z4[(size_t)q * 16 + c4];
            sZ[(c4 * 4 + 0) * 64 + q] = v.x;
            sZ[(c4 * 4 + 1) * 64 + q] = v.y;
            sZ[(c4 * 4 + 2) * 64 + q] = v.z;
            sZ[(c4 * 4 + 3) * 64 + q] = v.w;
        }
    }

    // local q slot r in [0,4) -> global q = q0 + ty*4 + r
    float minv[4];
    int   mini[4];
    #pragma unroll
    for (int i = 0; i < 4; ++i) { minv[i] = CUDART_INF_F; mini[i] = 0; }

    for (int kt = 0; kt < NK / TK; ++kt) {
        __syncthreads();  // previous tile compute done (and sZ visible on kt==0)
        // Load W tile transposed: sW[d][k] = W[kt*128+k][d]
        {
            const float4* W4 = reinterpret_cast<const float4*>(W) + (size_t)kt * TK * 16;
            #pragma unroll
            for (int rep = 0; rep < 8; ++rep) {
                int idx = rep * 256 + tid;
                int c4 = idx >> 7, k = idx & 127;
                float4 v = W4[(size_t)k * 16 + c4];
                sW[(c4 * 4 + 0) * 128 + k] = v.x;
                sW[(c4 * 4 + 1) * 128 + k] = v.y;
                sW[(c4 * 4 + 2) * 128 + k] = v.z;
                sW[(c4 * 4 + 3) * 128 + k] = v.w;
            }
            if (tid < 128) sw2[tid] = g_w2[kt * 128 + tid];
        }
        __syncthreads();

        ull accD[8], accA[8];   // [qp*4 + kp], qp in 0..1, kp in 0..3
        #pragma unroll
        for (int i = 0; i < 8; ++i) { accD[i] = 0ull; accA[i] = 0ull; }

        #pragma unroll 8
        for (int d = 0; d < 64; ++d) {
            // B: codes tx*8 + {0..7} as 4 natural pairs -> 2 x LDS.128
            const ull* bp = reinterpret_cast<const ull*>(&sW[d * 128]) + tx * 4;
            ull b0 = bp[0], b1 = bp[1], b2 = bp[2], b3 = bp[3];
            // A: queries ty*4 + {0..3} as 2 natural pairs -> 1 x LDS.128
            const ull* ap = reinterpret_cast<const ull*>(&sZ[d * 64]) + ty * 2;
            ull a0 = ap[0], a1 = ap[1];
            ull s0 = swap2(a0), s1 = swap2(a1);

            fma2(accD[0], a0, b0);  fma2(accA[0], s0, b0);
            fma2(accD[1], a0, b1);  fma2(accA[1], s0, b1);
            fma2(accD[2], a0, b2);  fma2(accA[2], s0, b2);
            fma2(accD[3], a0, b3);  fma2(accA[3], s0, b3);
            fma2(accD[4], a1, b0);  fma2(accA[4], s1, b0);
            fma2(accD[5], a1, b1);  fma2(accA[5], s1, b1);
            fma2(accD[6], a1, b2);  fma2(accA[6], s1, b2);
            fma2(accD[7], a1, b3);  fma2(accA[7], s1, b3);
        }

        // epilogue. accD=(qe*ke,qo*ko), accA=(qo*ke,qe*ko).
        // kj ascending, ke before ko, strict < : lowest index wins ties.
        int kbase = kt * 128 + tx * 8;
        #pragma unroll
        for (int qp = 0; qp < 2; ++qp) {
            #pragma unroll
            for (int kj = 0; kj < 4; ++kj) {
                float de, dh, ae, ah;
                unpack2(accD[qp * 4 + kj], de, dh);
                unpack2(accA[qp * 4 + kj], ae, ah);
                float w2e = sw2[tx * 8 + kj * 2];
                float w2o = sw2[tx * 8 + kj * 2 + 1];
                int ke = kbase + kj * 2;
                // q_even (slot 2qp):  (ke: de) (ko: ah)
                float se0 = fmaf(-2.0f, de, w2e);
                float se1 = fmaf(-2.0f, ah, w2o);
                if (se0 < minv[qp * 2]) { minv[qp * 2] = se0; mini[qp * 2] = ke; }
                if (se1 < minv[qp * 2]) { minv[qp * 2] = se1; mini[qp * 2] = ke + 1; }
                // q_odd (slot 2qp+1): (ke: ae) (ko: dh)
                float so0 = fmaf(-2.0f, ae, w2e);
                float so1 = fmaf(-2.0f, dh, w2o);
                if (so0 < minv[qp * 2 + 1]) { minv[qp * 2 + 1] = so0; mini[qp * 2 + 1] = ke; }
                if (so1 < minv[qp * 2 + 1]) { minv[qp * 2 + 1] = so1; mini[qp * 2 + 1] = ke + 1; }
            }
        }
    }

    // reduce across the 16 tx-threads (same half-warp, width 16)
    #pragma unroll
    for (int off = 8; off > 0; off >>= 1) {
        #pragma unroll
        for (int r = 0; r < 4; ++r) {
            float ov = __shfl_down_sync(0xffffffffu, minv[r], off, 16);
            int   oi = __shfl_down_sync(0xffffffffu, mini[r], off, 16);
            if (ov < minv[r] || (ov == minv[r] && oi < mini[r])) {
                minv[r] = ov; mini[r] = oi;
            }
        }
    }
    if (tx == 0) {
        #pragma unroll
        for (int r = 0; r < 4; ++r)
            g_enc[q0 + ty * 4 + r] = mini[r];
    }
}

// ------------------------- kernel 4: scatter / z_q / loss ------------------
__global__ void k_scatter(const float* __restrict__ W, float* __restrict__ out) {
    int warp = (blockIdx.x * blockDim.x + threadIdx.x) >> 5;
    int lane = threadIdx.x & 31;
    if (warp >= NQ) return;
    int e = g_enc[warp];

    float2 wv = reinterpret_cast<const float2*>(W)[(size_t)e * 32 + lane];
    float2 zv = reinterpret_cast<const float2*>(g_zn)[(size_t)warp * 32 + lane];
    float d0 = wv.x - zv.x, d1 = wv.y - zv.y;
    reinterpret_cast<float2*>(out + ZQ_OFF)[(size_t)warp * 32 + lane] =
        make_float2(zv.x + d0, zv.y + d1);

    atomicAdd(&g_es[(size_t)e * 64 + 2 * lane],     zv.x);
    atomicAdd(&g_es[(size_t)e * 64 + 2 * lane + 1], zv.y);

    float part = d0 * d0 + d1 * d1;
    #pragma unroll
    for (int off = 16; off > 0; off >>= 1)
        part += __shfl_xor_sync(0xffffffffu, part, off);
    if (lane == 0) {
        atomicAdd(&g_bins[e], 1.0f);
        atomicAdd(&g_loss, (double)part);
        out[ENC_OFF + warp] = (float)e;
    }
}

// ------------------------- kernel 5: per-code EMA updates ------------------
__global__ void k_update(const float* __restrict__ W,
                         const float* __restrict__ CS,
                         const float* __restrict__ EA,
                         float* __restrict__ out) {
    int warp = (blockIdx.x * blockDim.x + threadIdx.x) >> 5;
    int lane = threadIdx.x & 31;
    if (blockIdx.x == 0 && threadIdx.x == 0) {
        out[LOSS_OFF] = (float)(0.25 * (g_loss / (double)((size_t)NQ * DIM)));
    }
    if (warp >= NK) return;
    int k = warp;

    float b = g_bins[k];
    float2 es = reinterpret_cast<const float2*>(g_es)[(size_t)k * 32 + lane];
    float2 ea = reinterpret_cast<const float2*>(EA)[(size_t)k * 32 + lane];

    out[EA_OFF + (size_t)k * 64 + 2 * lane]     = ea.x * 0.99f + 0.01f * es.x;
    out[EA_OFF + (size_t)k * 64 + 2 * lane + 1] = ea.y * 0.99f + 0.01f * es.y;

    float bc = (b == 0.0f) ? 1.0f : b;
    float vx = es.x / bc, vy = es.y / bc;
    float ss = vx * vx + vy * vy;
    #pragma unroll
    for (int off = 16; off > 0; off >>= 1)
        ss += __shfl_xor_sync(0xffffffffu, ss, off);
    float inv = 1.0f / fmaxf(sqrtf(ss), 1e-12f);

    float2 wv = reinterpret_cast<const float2*>(W)[(size_t)k * 32 + lane];
    float enx = (b == 0.0f) ? wv.x : vx * inv;
    float eny = (b == 0.0f) ? wv.y : vy * inv;

    float nwx = wv.x * 0.99f + 0.01f * enx;
    float nwy = wv.y * 0.99f + 0.01f * eny;
    float ss2 = nwx * nwx + nwy * nwy;
    #pragma unroll
    for (int off = 16; off > 0; off >>= 1)
        ss2 += __shfl_xor_sync(0xffffffffu, ss2, off);
    float inv2 = 1.0f / fmaxf(sqrtf(ss2), 1e-12f);

    out[W_OFF + (size_t)k * 64 + 2 * lane]     = nwx * inv2;
    out[W_OFF + (size_t)k * 64 + 2 * lane + 1] = nwy * inv2;

    if (lane == 0) out[CS_OFF + k] = CS[k] * 0.99f + 0.01f * b;
}

// ------------------------- launch -------------------------------------------
extern "C" void kernel_launch(void* const* d_in, const int* in_sizes, int n_in,
                              void* d_out, int out_size) {
    const float* z  = (const float*)d_in[0];
    const float* w  = (const float*)d_in[1];
    const float* cs = (const float*)d_in[2];
    const float* ea = (const float*)d_in[3];
    float* out = (float*)d_out;

    const int smem_bytes = (64 * 64 + 64 * 128 + 128) * sizeof(float);  // 49664
    cudaFuncSetAttribute(k_argmin, cudaFuncAttributeMaxDynamicSharedMemorySize,
                         smem_bytes);

    k_zero<<<(NK * DIM + NK + 255) / 256, 256>>>();
    k_normz<<<NQ / 8, 256>>>(z);
    k_w2<<<NK / 8, 256>>>(w);
    k_argmin<<<NQ / TQ, 256, smem_bytes>>>(w);
    k_scatter<<<NQ / 8, 256>>>(w, out);
    k_update<<<NK / 8, 256>>>(w, cs, ea, out);
}

// round 8
// speedup vs baseline: 1.0002x; 1.0001x over previous
#include <cuda_runtime.h>
#include <cuda_bf16.h>
#include <math_constants.h>

// Problem constants
#define NQ   65536          // 16*4096 query vectors
#define DIM  64
#define NK   8192           // codebook size
#define TQ   64             // queries per block (argmin kernel)
#define TK   128            // codes per k-tile

// Output layout (flattened fp32, reference return order)
#define ZQ_OFF   0
#define LOSS_OFF 4194304
#define ENC_OFF  4194305
#define CS_OFF   4259841
#define EA_OFF   4268033
#define W_OFF    4792321

typedef unsigned long long ull;

// ------------------------- scratch (device globals; no allocs) ------------
__device__ float  g_zn[(size_t)NQ * DIM];     // normalized z (16 MB)
__device__ float  g_w2[NK];                   // per-code squared norm
__device__ int    g_enc[NQ];                  // argmin indices
__device__ float  g_bins[NK];                 // histogram
__device__ float  g_es[(size_t)NK * DIM];     // embed_sum (2 MB)
__device__ double g_loss;                     // loss accumulator

// ------------------------- f32x2 helpers ----------------------------------
__device__ __forceinline__ void fma2(ull& d, ull a, ull b) {
    asm("fma.rn.f32x2 %0, %1, %2, %0;" : "+l"(d) : "l"(a), "l"(b));
}
__device__ __forceinline__ void unpack2(ull v, float& lo, float& hi) {
    asm("mov.b64 {%0, %1}, %2;" : "=f"(lo), "=f"(hi) : "l"(v));
}
// swap halves of an f32x2 register pair (ALU-pipe PRMT copies)
__device__ __forceinline__ ull swap2(ull a) {
    unsigned lo, hi, slo, shi;
    asm("mov.b64 {%0, %1}, %2;" : "=r"(lo), "=r"(hi) : "l"(a));
    asm("prmt.b32 %0, %1, %1, 0x3210;" : "=r"(slo) : "r"(hi));
    asm("prmt.b32 %0, %1, %1, 0x3210;" : "=r"(shi) : "r"(lo));
    ull r;
    asm("mov.b64 %0, {%1, %2};" : "=l"(r) : "r"(slo), "r"(shi));
    return r;
}

// ------------------------- kernel 0: zero scratch --------------------------
__global__ void k_zero() {
    int idx = blockIdx.x * blockDim.x + threadIdx.x;
    if (idx < NK * DIM) g_es[idx] = 0.0f;
    int j = idx - NK * DIM;
    if (j >= 0 && j < NK) g_bins[j] = 0.0f;
    if (idx == 0) g_loss = 0.0;
}

// ------------------------- kernel 1: normalize z ---------------------------
__global__ void k_normz(const float* __restrict__ Z) {
    int warp = (blockIdx.x * blockDim.x + threadIdx.x) >> 5;
    int lane = threadIdx.x & 31;
    if (warp >= NQ) return;
    float2 v = reinterpret_cast<const float2*>(Z)[(size_t)warp * 32 + lane];
    float ss = v.x * v.x + v.y * v.y;
    #pragma unroll
    for (int off = 16; off > 0; off >>= 1)
        ss += __shfl_xor_sync(0xffffffffu, ss, off);
    float inv = 1.0f / fmaxf(sqrtf(ss), 1e-12f);
    reinterpret_cast<float2*>(g_zn)[(size_t)warp * 32 + lane] =
        make_float2(v.x * inv, v.y * inv);
}

// ------------------------- kernel 2: w2 ------------------------------------
__global__ void k_w2(const float* __restrict__ W) {
    int warp = (blockIdx.x * blockDim.x + threadIdx.x) >> 5;
    int lane = threadIdx.x & 31;
    if (warp >= NK) return;
    float2 v = reinterpret_cast<const float2*>(W)[(size_t)warp * 32 + lane];
    float ss = v.x * v.x + v.y * v.y;
    #pragma unroll
    for (int off = 16; off > 0; off >>= 1)
        ss += __shfl_xor_sync(0xffffffffu, ss, off);
    if (lane == 0) g_w2[warp] = ss;
}

// ------------------------- kernel 3: argmin (f32x2 SGEMM-argmin) -----------
// Block: 256 threads = 16(tx over k) x 16(ty over q). Micro-tile 4q x 8k
// (16 ull accs = 32 regs) -> low reg pressure -> 3 blocks/SM + prefetch slack.
// Z natural packed q-pairs, W natural packed k-pairs. Each 2q x 2k tile:
//   accD += a       * b   -> (qe*ke, qo*ko)
//   accA += swap(a) * b   -> (qo*ke, qe*ko)
__global__ __launch_bounds__(256, 3)
void k_argmin(const float* __restrict__ W) {
    extern __shared__ float sm[];
    float* sZ  = sm;                      // 64 * 64 floats  (d-major, q rows)
    float* sW  = sm + 64 * 64;            // 64 * 128 floats (d-major, k rows)
    float* sw2 = sW + 64 * 128;           // 128 floats

    const int tid = threadIdx.x;
    const int tx = tid & 15;
    const int ty = tid >> 4;
    const int q0 = blockIdx.x * TQ;

    // Load Z tile transposed: sZ[d][q] = zn[q0+q][d], q in [0,64)
    {
        const float4* Z4 = reinterpret_cast<const float4*>(g_zn) + (size_t)q0 * 16;
        #pragma unroll
        for (int rep = 0; rep < 4; ++rep) {
            int idx = rep * 256 + tid;          // 1024 float4 total
            int c4 = idx >> 6, q = idx & 63;
            float4 v = Z4[(size_t)q * 16 + c4];
            sZ[(c4 * 4 + 0) * 64 + q] = v.x;
            sZ[(c4 * 4 + 1) * 64 + q] = v.y;
            sZ[(c4 * 4 + 2) * 64 + q] = v.z;
            sZ[(c4 * 4 + 3) * 64 + q] = v.w;
        }
    }

    // local q slot r in [0,4) -> global q = q0 + ty*4 + r
    float minv[4];
    int   mini[4];
    #pragma unroll
    for (int i = 0; i < 4; ++i) { minv[i] = CUDART_INF_F; mini[i] = 0; }

    for (int kt = 0; kt < NK / TK; ++kt) {
        __syncthreads();  // previous tile compute done (and sZ visible on kt==0)
        // Load W tile transposed: sW[d][k] = W[kt*128+k][d]
        {
            const float4* W4 = reinterpret_cast<const float4*>(W) + (size_t)kt * TK * 16;
            #pragma unroll
            for (int rep = 0; rep < 8; ++rep) {
                int idx = rep * 256 + tid;
                int c4 = idx >> 7, k = idx & 127;
                float4 v = W4[(size_t)k * 16 + c4];
                sW[(c4 * 4 + 0) * 128 + k] = v.x;
                sW[(c4 * 4 + 1) * 128 + k] = v.y;
                sW[(c4 * 4 + 2) * 128 + k] = v.z;
                sW[(c4 * 4 + 3) * 128 + k] = v.w;
            }
            if (tid < 128) sw2[tid] = g_w2[kt * 128 + tid];
        }
        __syncthreads();

        ull accD[8], accA[8];   // [qp*4 + kp], qp in 0..1, kp in 0..3
        #pragma unroll
        for (int i = 0; i < 8; ++i) { accD[i] = 0ull; accA[i] = 0ull; }

        #pragma unroll 8
        for (int d = 0; d < 64; ++d) {
            // B: codes tx*8 + {0..7} as 4 natural pairs -> 2 x LDS.128
            const ull* bp = reinterpret_cast<const ull*>(&sW[d * 128]) + tx * 4;
            ull b0 = bp[0], b1 = bp[1], b2 = bp[2], b3 = bp[3];
            // A: queries ty*4 + {0..3} as 2 natural pairs -> 1 x LDS.128
            const ull* ap = reinterpret_cast<const ull*>(&sZ[d * 64]) + ty * 2;
            ull a0 = ap[0], a1 = ap[1];
            ull s0 = swap2(a0), s1 = swap2(a1);

            fma2(accD[0], a0, b0);  fma2(accA[0], s0, b0);
            fma2(accD[1], a0, b1);  fma2(accA[1], s0, b1);
            fma2(accD[2], a0, b2);  fma2(accA[2], s0, b2);
            fma2(accD[3], a0, b3);  fma2(accA[3], s0, b3);
            fma2(accD[4], a1, b0);  fma2(accA[4], s1, b0);
            fma2(accD[5], a1, b1);  fma2(accA[5], s1, b1);
            fma2(accD[6], a1, b2);  fma2(accA[6], s1, b2);
            fma2(accD[7], a1, b3);  fma2(accA[7], s1, b3);
        }

        // epilogue. accD=(qe*ke,qo*ko), accA=(qo*ke,qe*ko).
        // kj ascending, ke before ko, strict < : lowest index wins ties.
        int kbase = kt * 128 + tx * 8;
        #pragma unroll
        for (int qp = 0; qp < 2; ++qp) {
            #pragma unroll
            for (int kj = 0; kj < 4; ++kj) {
                float de, dh, ae, ah;
                unpack2(accD[qp * 4 + kj], de, dh);
                unpack2(accA[qp * 4 + kj], ae, ah);
                float w2e = sw2[tx * 8 + kj * 2];
                float w2o = sw2[tx * 8 + kj * 2 + 1];
                int ke = kbase + kj * 2;
                // q_even (slot 2qp):  (ke: de) (ko: ah)
                float se0 = fmaf(-2.0f, de, w2e);
                float se1 = fmaf(-2.0f, ah, w2o);
                if (se0 < minv[qp * 2]) { minv[qp * 2] = se0; mini[qp * 2] = ke; }
                if (se1 < minv[qp * 2]) { minv[qp * 2] = se1; mini[qp * 2] = ke + 1; }
                // q_odd (slot 2qp+1): (ke: ae) (ko: dh)
                float so0 = fmaf(-2.0f, ae, w2e);
                float so1 = fmaf(-2.0f, dh, w2o);
                if (so0 < minv[qp * 2 + 1]) { minv[qp * 2 + 1] = so0; mini[qp * 2 + 1] = ke; }
                if (so1 < minv[qp * 2 + 1]) { minv[qp * 2 + 1] = so1; mini[qp * 2 + 1] = ke + 1; }
            }
        }
    }

    // reduce across the 16 tx-threads (same half-warp, width 16)
    #pragma unroll
    for (int off = 8; off > 0; off >>= 1) {
        #pragma unroll
        for (int r = 0; r < 4; ++r) {
            float ov = __shfl_down_sync(0xffffffffu, minv[r], off, 16);
            int   oi = __shfl_down_sync(0xffffffffu, mini[r], off, 16);
            if (ov < minv[r] || (ov == minv[r] && oi < mini[r])) {
                minv[r] = ov; mini[r] = oi;
            }
        }
    }
    if (tx == 0) {
        #pragma unroll
        for (int r = 0; r < 4; ++r)
            g_enc[q0 + ty * 4 + r] = mini[r];
    }
}

// ------------------------- kernel 4: scatter / z_q / loss ------------------
__global__ void k_scatter(const float* __restrict__ W, float* __restrict__ out) {
    int warp = (blockIdx.x * blockDim.x + threadIdx.x) >> 5;
    int lane = threadIdx.x & 31;
    if (warp >= NQ) return;
    int e = g_enc[warp];

    float2 wv = reinterpret_cast<const float2*>(W)[(size_t)e * 32 + lane];
    float2 zv = reinterpret_cast<const float2*>(g_zn)[(size_t)warp * 32 + lane];
    float d0 = wv.x - zv.x, d1 = wv.y - zv.y;
    reinterpret_cast<float2*>(out + ZQ_OFF)[(size_t)warp * 32 + lane] =
        make_float2(zv.x + d0, zv.y + d1);

    atomicAdd(&g_es[(size_t)e * 64 + 2 * lane],     zv.x);
    atomicAdd(&g_es[(size_t)e * 64 + 2 * lane + 1], zv.y);

    float part = d0 * d0 + d1 * d1;
    #pragma unroll
    for (int off = 16; off > 0; off >>= 1)
        part += __shfl_xor_sync(0xffffffffu, part, off);
    if (lane == 0) {
        atomicAdd(&g_bins[e], 1.0f);
        atomicAdd(&g_loss, (double)part);
        out[ENC_OFF + warp] = (float)e;
    }
}

// ------------------------- kernel 5: per-code EMA updates ------------------
__global__ void k_update(const float* __restrict__ W,
                         const float* __restrict__ CS,
                         const float* __restrict__ EA,
                         float* __restrict__ out) {
    int warp = (blockIdx.x * blockDim.x + threadIdx.x) >> 5;
    int lane = threadIdx.x & 31;
    if (blockIdx.x == 0 && threadIdx.x == 0) {
        out[LOSS_OFF] = (float)(0.25 * (g_loss / (double)((size_t)NQ * DIM)));
    }
    if (warp >= NK) return;
    int k = warp;

    float b = g_bins[k];
    float2 es = reinterpret_cast<const float2*>(g_es)[(size_t)k * 32 + lane];
    float2 ea = reinterpret_cast<const float2*>(EA)[(size_t)k * 32 + lane];

    out[EA_OFF + (size_t)k * 64 + 2 * lane]     = ea.x * 0.99f + 0.01f * es.x;
    out[EA_OFF + (size_t)k * 64 + 2 * lane + 1] = ea.y * 0.99f + 0.01f * es.y;

    float bc = (b == 0.0f) ? 1.0f : b;
    float vx = es.x / bc, vy = es.y / bc;
    float ss = vx * vx + vy * vy;
    #pragma unroll
    for (int off = 16; off > 0; off >>= 1)
        ss += __shfl_xor_sync(0xffffffffu, ss, off);
    float inv = 1.0f / fmaxf(sqrtf(ss), 1e-12f);

    float2 wv = reinterpret_cast<const float2*>(W)[(size_t)k * 32 + lane];
    float enx = (b == 0.0f) ? wv.x : vx * inv;
    float eny = (b == 0.0f) ? wv.y : vy * inv;

    float nwx = wv.x * 0.99f + 0.01f * enx;
    float nwy = wv.y * 0.99f + 0.01f * eny;
    float ss2 = nwx * nwx + nwy * nwy;
    #pragma unroll
    for (int off = 16; off > 0; off >>= 1)
        ss2 += __shfl_xor_sync(0xffffffffu, ss2, off);
    float inv2 = 1.0f / fmaxf(sqrtf(ss2), 1e-12f);

    out[W_OFF + (size_t)k * 64 + 2 * lane]     = nwx * inv2;
    out[W_OFF + (size_t)k * 64 + 2 * lane + 1] = nwy * inv2;

    if (lane == 0) out[CS_OFF + k] = CS[k] * 0.99f + 0.01f * b;
}

// ------------------------- launch -------------------------------------------
extern "C" void kernel_launch(void* const* d_in, const int* in_sizes, int n_in,
                              void* d_out, int out_size) {
    const float* z  = (const float*)d_in[0];
    const float* w  = (const float*)d_in[1];
    const float* cs = (const float*)d_in[2];
    const float* ea = (const float*)d_in[3];
    float* out = (float*)d_out;

    const int smem_bytes = (64 * 64 + 64 * 128 + 128) * sizeof(float);  // 49664
    cudaFuncSetAttribute(k_argmin, cudaFuncAttributeMaxDynamicSharedMemorySize,
                         smem_bytes);

    k_zero<<<(NK * DIM + NK + 255) / 256, 256>>>();
    k_normz<<<NQ / 8, 256>>>(z);
    k_w2<<<NK / 8, 256>>>(w);
    k_argmin<<<NQ / TQ, 256, smem_bytes>>>(w);
    k_scatter<<<NQ / 8, 256>>>(w, out);
    k_update<<<NK / 8, 256>>>(w, cs, ea, out);
}